// round 8
// baseline (speedup 1.0000x reference)
#include <cuda_runtime.h>
#include <math.h>

#define TILE_PAIRS 1152   // smem: 1152 pairs * 32B = 36,864 B
#define PAIR_DIV   1140   // msplit divisor; pps <= 1140, np8 <= 1144 <= TILE_PAIRS

typedef unsigned long long u64;
typedef unsigned int u32;

__device__ __forceinline__ u64 pk2(float a, float b) {
    u64 r; asm("mov.b64 %0, {%1, %2};" : "=l"(r) : "f"(a), "f"(b)); return r;
}

// One m-pair vs this thread's query: 3-fma dot chain + b2, then sign bytes via
// PRMT, all inside one asm block so the b64->b32 split is a pure rename.
// ctl=0x00FB places {sign(lane0),sign(lane1)} at bytes {0,1}; 0xFB00 at {2,3}.
__device__ __forceinline__ u32 pair_sign(u64 X, u64 Y, u64 Z, u64 C,
                                         u64 bx2, u64 by2, u64 bz2, u64 b2p,
                                         u32 ctl) {
    u32 q;
    asm("{\n\t"
        ".reg .b64 t;\n\t"
        ".reg .b32 lo, hi;\n\t"
        "fma.rn.f32x2 t, %1, %2, %3;\n\t"     // t  = bx*X + C
        "fma.rn.f32x2 t, %4, %5, t;\n\t"      // t += by*Y
        "fma.rn.f32x2 t, %6, %7, t;\n\t"      // t += bz*Z
        "add.rn.f32x2 t, t, %8;\n\t"          // t += b2   (= d2 - 0.25, per lane)
        "mov.b64 {lo, hi}, t;\n\t"
        "prmt.b32 %0, lo, hi, %9;\n\t"
        "}"
        : "=r"(q)
        : "l"(bx2), "l"(X), "l"(C),
          "l"(by2), "l"(Y),
          "l"(bz2), "l"(Z),
          "l"(b2p), "r"(ctl));
    return q;
}

__global__ void zero_kernel(float* out, int n) {
    int i = blockIdx.x * blockDim.x + threadIdx.x;
    if (i < n) out[i] = 0.0f;
}

// Count condition: s = b2 + (a2-0.25) - 2(x*bx + y*by + z*bz) = d2 - 0.25;
// count iff s < 0. Same class as reference's sqrt(max(d2,0)) <= 0.5 (measured
// rel_err ~8e-6 from ulp-level reassociation ties).
__global__ void __launch_bounds__(256, 6) count_kernel(
    const float* __restrict__ pc,   // queries [N,3]
    const float* __restrict__ pad,  // padding [M,3]
    int N, int M, int pairs, int pps, float* __restrict__ out)
{
    __shared__ ulonglong2 sh[2 * TILE_PAIRS];   // per pair: {X01,Y01},{Z01,C01}

    const float INF = __int_as_float(0x7f800000);

    int p0 = blockIdx.y * pps;
    int np = pairs - p0;
    if (np > pps) np = pps;
    int np8 = (np + 7) & ~7;                    // pad to multiple of 8 pairs

    // Stage + pack this slice directly from raw padding data.
    for (int i = threadIdx.x; i < np; i += 256) {
        int p  = p0 + i;
        int m0 = 2 * p, m1 = 2 * p + 1;
        float x0 = pad[3 * m0], y0 = pad[3 * m0 + 1], z0 = pad[3 * m0 + 2];
        float c0 = fmaf(x0, x0, fmaf(y0, y0, z0 * z0)) - 0.25f;
        float x1 = 0.f, y1 = 0.f, z1 = 0.f, c1 = INF;   // sentinel never counts
        if (m1 < M) {
            x1 = pad[3 * m1]; y1 = pad[3 * m1 + 1]; z1 = pad[3 * m1 + 2];
            c1 = fmaf(x1, x1, fmaf(y1, y1, z1 * z1)) - 0.25f;
        }
        sh[2 * i]     = make_ulonglong2(pk2(-2.f * x0, -2.f * x1),
                                        pk2(-2.f * y0, -2.f * y1));
        sh[2 * i + 1] = make_ulonglong2(pk2(-2.f * z0, -2.f * z1),
                                        pk2(c0, c1));
    }
    for (int i = np + threadIdx.x; i < np8; i += 256) {   // sentinel pad pairs
        sh[2 * i]     = make_ulonglong2(0ull, 0ull);
        sh[2 * i + 1] = make_ulonglong2(0ull, pk2(INF, INF));
    }
    __syncthreads();

    int n = blockIdx.x * 256 + threadIdx.x;
    float bx = 0.f, by = 0.f, bz = 0.f, b2 = INF;  // inactive: never counts
    if (n < N) {
        bx = pc[3 * n]; by = pc[3 * n + 1]; bz = pc[3 * n + 2];
        b2 = fmaf(bx, bx, fmaf(by, by, bz * bz));
    }
    const u64 bx2 = pk2(bx, bx), by2 = pk2(by, by), bz2 = pk2(bz, bz),
              b2p = pk2(b2, b2);

    // 4 byte-accumulators; each byte incremented once per 8-pair iteration
    // (<= 143 for pps <= 1140) => no byte overflow.
    u32 aA = 0, aB = 0, aC = 0, aD = 0;
    for (int j = 0; j < np8; j += 8) {
        const ulonglong2* P = sh + 2 * j;
        {
            ulonglong2 A0 = P[0], B0 = P[1], A1 = P[2], B1 = P[3];
            u32 q0 = pair_sign(A0.x, A0.y, B0.x, B0.y, bx2, by2, bz2, b2p, 0x00FBu);
            u32 q1 = pair_sign(A1.x, A1.y, B1.x, B1.y, bx2, by2, bz2, b2p, 0xFB00u);
            aA += (q0 & 0x00000101u) + (q1 & 0x01010000u);
        }
        {
            ulonglong2 A0 = P[4], B0 = P[5], A1 = P[6], B1 = P[7];
            u32 q0 = pair_sign(A0.x, A0.y, B0.x, B0.y, bx2, by2, bz2, b2p, 0x00FBu);
            u32 q1 = pair_sign(A1.x, A1.y, B1.x, B1.y, bx2, by2, bz2, b2p, 0xFB00u);
            aB += (q0 & 0x00000101u) + (q1 & 0x01010000u);
        }
        {
            ulonglong2 A0 = P[8], B0 = P[9], A1 = P[10], B1 = P[11];
            u32 q0 = pair_sign(A0.x, A0.y, B0.x, B0.y, bx2, by2, bz2, b2p, 0x00FBu);
            u32 q1 = pair_sign(A1.x, A1.y, B1.x, B1.y, bx2, by2, bz2, b2p, 0xFB00u);
            aC += (q0 & 0x00000101u) + (q1 & 0x01010000u);
        }
        {
            ulonglong2 A0 = P[12], B0 = P[13], A1 = P[14], B1 = P[15];
            u32 q0 = pair_sign(A0.x, A0.y, B0.x, B0.y, bx2, by2, bz2, b2p, 0x00FBu);
            u32 q1 = pair_sign(A1.x, A1.y, B1.x, B1.y, bx2, by2, bz2, b2p, 0xFB00u);
            aD += (q0 & 0x00000101u) + (q1 & 0x01010000u);
        }
    }

    // Unsigned per-byte reduction (bytes <= 143).
    u32 cnt = (aA & 0xFFu) + ((aA >> 8) & 0xFFu) + ((aA >> 16) & 0xFFu) + (aA >> 24)
            + (aB & 0xFFu) + ((aB >> 8) & 0xFFu) + ((aB >> 16) & 0xFFu) + (aB >> 24)
            + (aC & 0xFFu) + ((aC >> 8) & 0xFFu) + ((aC >> 16) & 0xFFu) + (aC >> 24)
            + (aD & 0xFFu) + ((aD >> 8) & 0xFFu) + ((aD >> 16) & 0xFFu) + (aD >> 24);

    if (n < N) atomicAdd(out + n, (float)cnt);
}

extern "C" void kernel_launch(void* const* d_in, const int* in_sizes, int n_in,
                              void* d_out, int out_size) {
    // The input with 3*out_size elements IS the pointcloud (output rows = N).
    int N = out_size;
    const float* pc;
    const float* pad;
    int M;
    if (in_sizes[0] == 3 * out_size) {
        pc  = (const float*)d_in[0];
        pad = (const float*)d_in[1];
        M   = in_sizes[1] / 3;
    } else {
        pc  = (const float*)d_in[1];
        pad = (const float*)d_in[0];
        M   = in_sizes[0] / 3;
    }

    int pairs  = (M + 1) / 2;                       // 12500
    int msplit = (pairs + PAIR_DIV - 1) / PAIR_DIV; // 11
    if (msplit < 1) msplit = 1;
    int pps    = (pairs + msplit - 1) / msplit;     // 1137 (<= 1140)

    float* out = (float*)d_out;
    zero_kernel<<<(out_size + 255) / 256, 256>>>(out, out_size);
    dim3 grid((N + 255) / 256, msplit);             // 79 x 11 = 869 blocks
    count_kernel<<<grid, 256>>>(pc, pad, N, M, pairs, pps, out);
}

// round 9
// speedup vs baseline: 1.4465x; 1.4465x over previous
#include <cuda_runtime.h>
#include <math.h>

#define THREADS    128
#define QPT        4                 // queries per thread
#define QPB        (THREADS * QPT)   // 512 queries per block
#define TILE_PAIRS 572               // smem tile: 572 * 32B = 18,304 B
#define MAX_PPS    572               // pps <= 572; 572/4 = 143 <= 255 byte-ctr bound

typedef unsigned long long u64;
typedef unsigned int u32;

__device__ __forceinline__ u64 pk2(float a, float b) {
    u64 r; asm("mov.b64 %0, {%1, %2};" : "=l"(r) : "f"(a), "f"(b)); return r;
}

// One m-pair (2 m's in f32x2 lanes) vs one query: s = d2 - 0.25 per lane,
// then sign bytes via PRMT (one fused asm block; b64->b32 split is a rename).
// ctl 0x00FB -> sign bytes at {0,1}; 0xFB00 -> at {2,3}.
__device__ __forceinline__ u32 pair_sign(u64 X, u64 Y, u64 Z, u64 C,
                                         u64 bx2, u64 by2, u64 bz2, u64 b2p,
                                         u32 ctl) {
    u32 q;
    asm("{\n\t"
        ".reg .b64 t;\n\t"
        ".reg .b32 lo, hi;\n\t"
        "fma.rn.f32x2 t, %1, %2, %3;\n\t"     // t  = bx*X + C
        "fma.rn.f32x2 t, %4, %5, t;\n\t"      // t += by*Y
        "fma.rn.f32x2 t, %6, %7, t;\n\t"      // t += bz*Z
        "add.rn.f32x2 t, t, %8;\n\t"          // t += b2
        "mov.b64 {lo, hi}, t;\n\t"
        "prmt.b32 %0, lo, hi, %9;\n\t"
        "}"
        : "=r"(q)
        : "l"(bx2), "l"(X), "l"(C),
          "l"(by2), "l"(Y),
          "l"(bz2), "l"(Z),
          "l"(b2p), "r"(ctl));
    return q;
}

__global__ void zero_kernel(float* out, int n) {
    int i = blockIdx.x * blockDim.x + threadIdx.x;
    if (i < n) out[i] = 0.0f;
}

// s = b2 + (a2-0.25) - 2(x*bx+y*by+z*bz) = d2 - 0.25; count iff s < 0.
// Matches reference's sqrt(max(d2,0)) <= 0.5 up to reassociation ties
// (measured 8.1e-6).
__global__ void __launch_bounds__(THREADS) count_kernel(
    const float* __restrict__ pc,   // queries [N,3]
    const float* __restrict__ pad,  // padding [M,3]
    int N, int M, int pairs, int pps, float* __restrict__ out)
{
    __shared__ ulonglong2 sh[2 * TILE_PAIRS];   // per pair: {X01,Y01},{Z01,C01}
    const float INF = __int_as_float(0x7f800000);

    int p0 = blockIdx.y * pps;
    int np = pairs - p0;
    if (np > pps) np = pps;
    int np4 = (np + 3) & ~3;

    // Stage + pack this m-slice from raw padding data.
    for (int i = threadIdx.x; i < np; i += THREADS) {
        int p  = p0 + i;
        int m0 = 2 * p, m1 = 2 * p + 1;
        float x0 = pad[3 * m0], y0 = pad[3 * m0 + 1], z0 = pad[3 * m0 + 2];
        float c0 = fmaf(x0, x0, fmaf(y0, y0, z0 * z0)) - 0.25f;
        float x1 = 0.f, y1 = 0.f, z1 = 0.f, c1 = INF;   // sentinel never counts
        if (m1 < M) {
            x1 = pad[3 * m1]; y1 = pad[3 * m1 + 1]; z1 = pad[3 * m1 + 2];
            c1 = fmaf(x1, x1, fmaf(y1, y1, z1 * z1)) - 0.25f;
        }
        sh[2 * i]     = make_ulonglong2(pk2(-2.f * x0, -2.f * x1),
                                        pk2(-2.f * y0, -2.f * y1));
        sh[2 * i + 1] = make_ulonglong2(pk2(-2.f * z0, -2.f * z1),
                                        pk2(c0, c1));
    }
    for (int i = np + threadIdx.x; i < np4; i += THREADS) {
        sh[2 * i]     = make_ulonglong2(0ull, 0ull);
        sh[2 * i + 1] = make_ulonglong2(0ull, pk2(INF, INF));
    }
    __syncthreads();

    // 4 queries per thread: n0 + k*THREADS.
    int n0 = blockIdx.x * QPB + threadIdx.x;
    u64 bx2[QPT], by2[QPT], bz2[QPT], b2p[QPT];
#pragma unroll
    for (int k = 0; k < QPT; ++k) {
        int n = n0 + k * THREADS;
        float bx = 0.f, by = 0.f, bz = 0.f, b2 = INF;
        if (n < N) {
            bx = pc[3 * n]; by = pc[3 * n + 1]; bz = pc[3 * n + 2];
            b2 = fmaf(bx, bx, fmaf(by, by, bz * bz));
        }
        bx2[k] = pk2(bx, bx); by2[k] = pk2(by, by);
        bz2[k] = pk2(bz, bz); b2p[k] = pk2(b2, b2);
    }

    // acc[2s+0]: queries 0,1 for m-pair slot s (bytes 0,1 / 2,3);
    // acc[2s+1]: queries 2,3. Each byte +1 per 4-pair iter (<=143) — no overflow.
    u32 acc[8] = {0, 0, 0, 0, 0, 0, 0, 0};
    for (int j = 0; j < np4; j += 4) {
        const ulonglong2* P = sh + 2 * j;
#pragma unroll
        for (int s = 0; s < 4; ++s) {
            ulonglong2 A = P[2 * s], B = P[2 * s + 1];
            u32 q0 = pair_sign(A.x, A.y, B.x, B.y,
                               bx2[0], by2[0], bz2[0], b2p[0], 0x00FBu);
            u32 q1 = pair_sign(A.x, A.y, B.x, B.y,
                               bx2[1], by2[1], bz2[1], b2p[1], 0xFB00u);
            acc[2 * s] += (q0 & 0x00000101u) + (q1 & 0x01010000u);
            u32 q2 = pair_sign(A.x, A.y, B.x, B.y,
                               bx2[2], by2[2], bz2[2], b2p[2], 0x00FBu);
            u32 q3 = pair_sign(A.x, A.y, B.x, B.y,
                               bx2[3], by2[3], bz2[3], b2p[3], 0xFB00u);
            acc[2 * s + 1] += (q2 & 0x00000101u) + (q3 & 0x01010000u);
        }
    }

    // Unsigned per-byte reduction, separated per query (bytes <= 143).
    u32 c[QPT] = {0, 0, 0, 0};
#pragma unroll
    for (int s = 0; s < 4; ++s) {
        u32 a = acc[2 * s], b = acc[2 * s + 1];
        c[0] += (a & 0xFFu) + ((a >> 8) & 0xFFu);
        c[1] += ((a >> 16) & 0xFFu) + (a >> 24);
        c[2] += (b & 0xFFu) + ((b >> 8) & 0xFFu);
        c[3] += ((b >> 16) & 0xFFu) + (b >> 24);
    }
#pragma unroll
    for (int k = 0; k < QPT; ++k) {
        int n = n0 + k * THREADS;
        if (n < N) atomicAdd(out + n, (float)c[k]);
    }
}

extern "C" void kernel_launch(void* const* d_in, const int* in_sizes, int n_in,
                              void* d_out, int out_size) {
    // The input with 3*out_size elements IS the pointcloud (output rows = N).
    int N = out_size;
    const float* pc;
    const float* pad;
    int M;
    if (in_sizes[0] == 3 * out_size) {
        pc  = (const float*)d_in[0];
        pad = (const float*)d_in[1];
        M   = in_sizes[1] / 3;
    } else {
        pc  = (const float*)d_in[1];
        pad = (const float*)d_in[0];
        M   = in_sizes[0] / 3;
    }

    int pairs  = (M + 1) / 2;                        // 12500
    int msplit = (pairs + MAX_PPS - 1) / MAX_PPS;    // 22
    if (msplit < 1) msplit = 1;
    int pps    = (pairs + msplit - 1) / msplit;      // 569 (<= 572)

    int nx = (N + QPB - 1) / QPB;                    // 40
    float* out = (float*)d_out;
    zero_kernel<<<(out_size + 255) / 256, 256>>>(out, out_size);
    dim3 grid(nx, msplit);                           // 40 x 22 = 880 blocks
    count_kernel<<<grid, THREADS>>>(pc, pad, N, M, pairs, pps, out);
}

// round 10
// speedup vs baseline: 1.4471x; 1.0004x over previous
#include <cuda_runtime.h>
#include <math.h>

#define THREADS    128
#define QPT        4                 // queries per thread
#define QPB        (THREADS * QPT)   // 512 queries per block
#define TILE_PAIRS 384               // smem tile: 384 * 32B = 12,288 B
#define MAX_PPS    380               // pps <= 380; ceil(380/4)=95 <= 255 byte bound

typedef unsigned long long u64;
typedef unsigned int u32;

__device__ __forceinline__ u64 pk2(float a, float b) {
    u64 r; asm("mov.b64 %0, {%1, %2};" : "=l"(r) : "f"(a), "f"(b)); return r;
}

// One m-pair (2 m's in f32x2 lanes) vs one query: s = d2 - 0.25 per lane,
// then sign bytes via PRMT (one fused asm block; b64->b32 split is a rename).
// ctl 0x00FB -> sign bytes at {0,1}; 0xFB00 -> at {2,3}.
__device__ __forceinline__ u32 pair_sign(u64 X, u64 Y, u64 Z, u64 C,
                                         u64 bx2, u64 by2, u64 bz2, u64 b2p,
                                         u32 ctl) {
    u32 q;
    asm("{\n\t"
        ".reg .b64 t;\n\t"
        ".reg .b32 lo, hi;\n\t"
        "fma.rn.f32x2 t, %1, %2, %3;\n\t"     // t  = bx*X + C
        "fma.rn.f32x2 t, %4, %5, t;\n\t"      // t += by*Y
        "fma.rn.f32x2 t, %6, %7, t;\n\t"      // t += bz*Z
        "add.rn.f32x2 t, t, %8;\n\t"          // t += b2
        "mov.b64 {lo, hi}, t;\n\t"
        "prmt.b32 %0, lo, hi, %9;\n\t"
        "}"
        : "=r"(q)
        : "l"(bx2), "l"(X), "l"(C),
          "l"(by2), "l"(Y),
          "l"(bz2), "l"(Z),
          "l"(b2p), "r"(ctl));
    return q;
}

// s = b2 + (a2-0.25) - 2(x*bx+y*by+z*bz) = d2 - 0.25; count iff s < 0.
// Matches reference's sqrt(max(d2,0)) <= 0.5 up to reassociation ties
// (measured 8.1e-6).
__global__ void __launch_bounds__(THREADS, 9) count_kernel(
    const float* __restrict__ pc,   // queries [N,3]
    const float* __restrict__ pad,  // padding [M,3]
    int N, int M, int pairs, int pps, float* __restrict__ out)
{
    __shared__ ulonglong2 sh[2 * TILE_PAIRS];   // per pair: {X01,Y01},{Z01,C01}
    const float INF = __int_as_float(0x7f800000);

    int p0 = blockIdx.y * pps;
    int np = pairs - p0;
    if (np > pps) np = pps;
    int np4 = (np + 3) & ~3;

    // Stage + pack this m-slice from raw padding data.
    for (int i = threadIdx.x; i < np; i += THREADS) {
        int p  = p0 + i;
        int m0 = 2 * p, m1 = 2 * p + 1;
        float x0 = pad[3 * m0], y0 = pad[3 * m0 + 1], z0 = pad[3 * m0 + 2];
        float c0 = fmaf(x0, x0, fmaf(y0, y0, z0 * z0)) - 0.25f;
        float x1 = 0.f, y1 = 0.f, z1 = 0.f, c1 = INF;   // sentinel never counts
        if (m1 < M) {
            x1 = pad[3 * m1]; y1 = pad[3 * m1 + 1]; z1 = pad[3 * m1 + 2];
            c1 = fmaf(x1, x1, fmaf(y1, y1, z1 * z1)) - 0.25f;
        }
        sh[2 * i]     = make_ulonglong2(pk2(-2.f * x0, -2.f * x1),
                                        pk2(-2.f * y0, -2.f * y1));
        sh[2 * i + 1] = make_ulonglong2(pk2(-2.f * z0, -2.f * z1),
                                        pk2(c0, c1));
    }
    for (int i = np + threadIdx.x; i < np4; i += THREADS) {
        sh[2 * i]     = make_ulonglong2(0ull, 0ull);
        sh[2 * i + 1] = make_ulonglong2(0ull, pk2(INF, INF));
    }
    __syncthreads();

    // 4 queries per thread: n0 + k*THREADS.
    int n0 = blockIdx.x * QPB + threadIdx.x;
    u64 bx2[QPT], by2[QPT], bz2[QPT], b2p[QPT];
#pragma unroll
    for (int k = 0; k < QPT; ++k) {
        int n = n0 + k * THREADS;
        float bx = 0.f, by = 0.f, bz = 0.f, b2 = INF;
        if (n < N) {
            bx = pc[3 * n]; by = pc[3 * n + 1]; bz = pc[3 * n + 2];
            b2 = fmaf(bx, bx, fmaf(by, by, bz * bz));
        }
        bx2[k] = pk2(bx, bx); by2[k] = pk2(by, by);
        bz2[k] = pk2(bz, bz); b2p[k] = pk2(b2, b2);
    }

    // acc[2s+0]: queries 0,1 for m-pair slot s (bytes 0,1 / 2,3);
    // acc[2s+1]: queries 2,3. Each byte +1 per 4-pair iter (<=95) — no overflow.
    u32 acc[8] = {0, 0, 0, 0, 0, 0, 0, 0};
    for (int j = 0; j < np4; j += 4) {
        const ulonglong2* P = sh + 2 * j;
#pragma unroll
        for (int s = 0; s < 4; ++s) {
            ulonglong2 A = P[2 * s], B = P[2 * s + 1];
            u32 q0 = pair_sign(A.x, A.y, B.x, B.y,
                               bx2[0], by2[0], bz2[0], b2p[0], 0x00FBu);
            u32 q1 = pair_sign(A.x, A.y, B.x, B.y,
                               bx2[1], by2[1], bz2[1], b2p[1], 0xFB00u);
            acc[2 * s] += (q0 & 0x00000101u) + (q1 & 0x01010000u);
            u32 q2 = pair_sign(A.x, A.y, B.x, B.y,
                               bx2[2], by2[2], bz2[2], b2p[2], 0x00FBu);
            u32 q3 = pair_sign(A.x, A.y, B.x, B.y,
                               bx2[3], by2[3], bz2[3], b2p[3], 0xFB00u);
            acc[2 * s + 1] += (q2 & 0x00000101u) + (q3 & 0x01010000u);
        }
    }

    // Unsigned per-byte reduction, separated per query (bytes <= 95).
    u32 c[QPT] = {0, 0, 0, 0};
#pragma unroll
    for (int s = 0; s < 4; ++s) {
        u32 a = acc[2 * s], b = acc[2 * s + 1];
        c[0] += (a & 0xFFu) + ((a >> 8) & 0xFFu);
        c[1] += ((a >> 16) & 0xFFu) + (a >> 24);
        c[2] += (b & 0xFFu) + ((b >> 8) & 0xFFu);
        c[3] += ((b >> 16) & 0xFFu) + (b >> 24);
    }
#pragma unroll
    for (int k = 0; k < QPT; ++k) {
        int n = n0 + k * THREADS;
        if (n < N) atomicAdd(out + n, (float)c[k]);
    }
}

extern "C" void kernel_launch(void* const* d_in, const int* in_sizes, int n_in,
                              void* d_out, int out_size) {
    // The input with 3*out_size elements IS the pointcloud (output rows = N).
    int N = out_size;
    const float* pc;
    const float* pad;
    int M;
    if (in_sizes[0] == 3 * out_size) {
        pc  = (const float*)d_in[0];
        pad = (const float*)d_in[1];
        M   = in_sizes[1] / 3;
    } else {
        pc  = (const float*)d_in[1];
        pad = (const float*)d_in[0];
        M   = in_sizes[0] / 3;
    }

    int pairs  = (M + 1) / 2;                        // 12500
    int msplit = (pairs + MAX_PPS - 1) / MAX_PPS;    // 33
    if (msplit < 1) msplit = 1;
    int pps    = (pairs + msplit - 1) / msplit;      // 379 (<= 380)

    int nx = (N + QPB - 1) / QPB;                    // 40
    float* out = (float*)d_out;
    // Zero output (atomic accumulation target); memset node is graph-capturable.
    cudaMemsetAsync(out, 0, (size_t)out_size * sizeof(float), 0);
    dim3 grid(nx, msplit);                           // 40 x 33 = 1320 blocks
    count_kernel<<<grid, THREADS>>>(pc, pad, N, M, pairs, pps, out);
}